// round 17
// baseline (speedup 1.0000x reference)
#include <cuda_runtime.h>
#include <cuda_bf16.h>
#include <cstdint>

#define NN 50000
#define EE 400000

// ---------------- scratch ----------------
__device__ float g_q[(size_t)NN * 256];
__device__ float g_k[(size_t)NN * 256];
__device__ float g_v[(size_t)NN * 256];
__device__ float g_e[(size_t)EE * 256];
__device__ float g_alpha[(size_t)EE * 2];
__device__ float g_amax[(size_t)NN * 2];
__device__ float g_asum[(size_t)NN * 2];

// ---------------- helpers ----------------
__device__ __forceinline__ void atomicMaxFloat(float* addr, float val) {
    if (val >= 0.0f) atomicMax((int*)addr, __float_as_int(val));
    else             atomicMin((unsigned int*)addr, __float_as_uint(val));
}

__device__ __forceinline__ float to_tf32(float x) {
    float r; asm("cvt.rna.tf32.f32 %0, %1;" : "=f"(r) : "f"(x)); return r;
}

__device__ __forceinline__ void mma_tf32(float* c, const float* a, const float* b) {
    asm volatile(
        "mma.sync.aligned.m16n8k8.row.col.f32.tf32.tf32.f32 "
        "{%0,%1,%2,%3}, {%4,%5,%6,%7}, {%8,%9}, {%0,%1,%2,%3};"
        : "+f"(c[0]), "+f"(c[1]), "+f"(c[2]), "+f"(c[3])
        : "r"(__float_as_uint(a[0])), "r"(__float_as_uint(a[1])),
          "r"(__float_as_uint(a[2])), "r"(__float_as_uint(a[3])),
          "r"(__float_as_uint(b[0])), "r"(__float_as_uint(b[1])));
}

// ---------------- K0: init ----------------
__global__ void init_kernel() {
    int i = blockIdx.x * blockDim.x + threadIdx.x;
    if (i < 2 * NN) {
        g_amax[i] = __int_as_float(0xff800000);
        g_asum[i] = 0.0f;
    }
}

// =====================================================================
// tf32 GEMM: BM=128, BN=256, BK=32, 512 threads (16 warps, 4x4).
// A tile fully resident in smem [128 x 256] (stride 260, conflict-free:
// 260 % 32 == 4 -> (g*4+i) covers all banks). B double-buffered
// [256 x 32] (stride 36). Register-bound at 1 CTA/SM, so smem is free.
// =====================================================================
#define AFULL 260
#define BSTR  36
#define A_WORDS (128 * AFULL)
#define B_WORDS (256 * BSTR)
#define SMEM_BYTES ((A_WORDS + 2 * B_WORDS) * 4)

__device__ __forceinline__ void fill_B(float* Bs, const float* __restrict__ W,
                                       int kt, int t) {
    int n = t & 255;
    int kh = t >> 8;            // 0..1, 16 k each
    #pragma unroll
    for (int j = 0; j < 16; j++) {
        Bs[n * BSTR + kh * 16 + j] = to_tf32(W[(size_t)(kt * 32 + kh * 16 + j) * 256 + n]);
    }
}

__device__ __forceinline__ void gemm_compute(const float* As, const float* Bs,
                                             float acc[2][8][4], int kt,
                                             int wm, int wn, int g, int i) {
    #pragma unroll
    for (int ks = 0; ks < 4; ks++) {
        int kb = ks * 8;
        float a[2][4];
        #pragma unroll
        for (int mm = 0; mm < 2; mm++) {
            int r = (wm * 32 + mm * 16 + g) * AFULL + kt * 32;
            a[mm][0] = As[r + kb + i];
            a[mm][1] = As[r + 8 * AFULL + kb + i];
            a[mm][2] = As[r + kb + i + 4];
            a[mm][3] = As[r + 8 * AFULL + kb + i + 4];
        }
        float b[8][2];
        #pragma unroll
        for (int nn = 0; nn < 8; nn++) {
            int cb = (wn * 64 + nn * 8 + g) * BSTR;
            b[nn][0] = Bs[cb + kb + i];
            b[nn][1] = Bs[cb + kb + i + 4];
        }
        #pragma unroll
        for (int mm = 0; mm < 2; mm++)
            #pragma unroll
            for (int nn = 0; nn < 8; nn++)
                mma_tf32(acc[mm][nn], a[mm], b[nn]);
    }
}

// ---------------- K1: node projections ----------------
__global__ __launch_bounds__(512) void node_proj_kernel(
    const float* __restrict__ x,
    const float* __restrict__ Wq, const float* __restrict__ bq,
    const float* __restrict__ Wk, const float* __restrict__ bk,
    const float* __restrict__ Wv, const float* __restrict__ bv,
    const float* __restrict__ Wskip, const float* __restrict__ bskip,
    float* __restrict__ out)
{
    extern __shared__ float smem[];
    float* As = smem;
    float* B0 = smem + A_WORDS;
    float* B1 = B0 + B_WORDS;

    const int wsel = blockIdx.x;
    const int m0 = blockIdx.y * 128;

    const float* W; const float* bias; float* dst;
    switch (wsel) {
        case 0:  W = Wq;    bias = bq;    dst = g_q; break;
        case 1:  W = Wk;    bias = bk;    dst = g_k; break;
        case 2:  W = Wv;    bias = bv;    dst = g_v; break;
        default: W = Wskip; bias = bskip; dst = out; break;
    }

    const int t = threadIdx.x;
    const int warp = t >> 5, lane = t & 31;
    const int wm = warp >> 2, wn = warp & 3;
    const int g = lane >> 2, i = lane & 3;

    // A fill: 16 steps, each warp reads a contiguous 512B row segment.
    #pragma unroll
    for (int j = 0; j < 16; j++) {
        int f = j * 512 + t;       // 0..8191
        int row = f >> 6;          // 0..127
        int c4 = f & 63;           // float4 column
        int rowg = m0 + row; if (rowg >= NN) rowg = NN - 1;
        float4 v = *(const float4*)&x[(size_t)rowg * 256 + c4 * 4];
        float4 o; o.x = to_tf32(v.x); o.y = to_tf32(v.y);
        o.z = to_tf32(v.z); o.w = to_tf32(v.w);
        *(float4*)&As[row * AFULL + c4 * 4] = o;
    }
    fill_B(B0, W, 0, t);
    __syncthreads();

    float acc[2][8][4];
    #pragma unroll
    for (int mm = 0; mm < 2; mm++)
        #pragma unroll
        for (int nn = 0; nn < 8; nn++)
            #pragma unroll
            for (int r = 0; r < 4; r++) acc[mm][nn][r] = 0.0f;

    #pragma unroll
    for (int kt = 0; kt < 8; kt++) {
        float* cur = (kt & 1) ? B1 : B0;
        float* nxt = (kt & 1) ? B0 : B1;
        if (kt < 7) fill_B(nxt, W, kt + 1, t);
        gemm_compute(As, cur, acc, kt, wm, wn, g, i);
        __syncthreads();
    }

    #pragma unroll
    for (int mm = 0; mm < 2; mm++) {
        #pragma unroll
        for (int nn = 0; nn < 8; nn++) {
            int cc = wn * 64 + nn * 8 + i * 2;
            float2 bv2 = *(const float2*)&bias[cc];
            int r0 = m0 + wm * 32 + mm * 16 + g;
            if (r0 < NN) {
                float2 o; o.x = acc[mm][nn][0] + bv2.x; o.y = acc[mm][nn][1] + bv2.y;
                *(float2*)&dst[(size_t)r0 * 256 + cc] = o;
            }
            if (r0 + 8 < NN) {
                float2 o; o.x = acc[mm][nn][2] + bv2.x; o.y = acc[mm][nn][3] + bv2.y;
                *(float2*)&dst[(size_t)(r0 + 8) * 256 + cc] = o;
            }
        }
    }
}

// ---------------- K2: edge GEMM + fused alpha ----------------
__global__ __launch_bounds__(512) void edge_kernel(
    const float* __restrict__ last_update, const float* __restrict__ t_arr,
    const float* __restrict__ msg, const int* __restrict__ ei,
    const float* __restrict__ Wt, const float* __restrict__ bt,
    const float* __restrict__ We)
{
    extern __shared__ float smem[];
    float* As = smem;
    float* B0 = smem + A_WORDS;
    float* B1 = B0 + B_WORDS;

    __shared__ float s_rel[128];
    __shared__ int   s_src[128], s_dst[128];
    __shared__ float s_wt[128], s_bt[128];
    __shared__ float s_alpha[256];               // [row][head]

    const int m0 = blockIdx.x * 128;             // EE % 128 == 0

    const int t = threadIdx.x;
    const int warp = t >> 5, lane = t & 31;
    const int wm = warp >> 2, wn = warp & 3;
    const int g = lane >> 2, i = lane & 3;

    if (t < 128) {
        s_wt[t] = Wt[t]; s_bt[t] = bt[t];
        int e = m0 + t;
        int sidx = ei[e];
        s_src[t] = sidx;
        s_dst[t] = ei[EE + e];
        s_rel[t] = last_update[sidx] - t_arr[e];
    }
    if (t < 256) s_alpha[t] = 0.0f;
    __syncthreads();

    // A fill: cols 0..127 = cos(rel*wt+bt), cols 128..255 = msg.
    #pragma unroll
    for (int j = 0; j < 16; j++) {
        int f = j * 512 + t;
        int row = f >> 6;
        int c4 = f & 63;
        float4 o;
        if (c4 < 32) {
            float rel = s_rel[row];
            int k = c4 * 4;
            o.x = to_tf32(__cosf(rel * s_wt[k + 0] + s_bt[k + 0]));
            o.y = to_tf32(__cosf(rel * s_wt[k + 1] + s_bt[k + 1]));
            o.z = to_tf32(__cosf(rel * s_wt[k + 2] + s_bt[k + 2]));
            o.w = to_tf32(__cosf(rel * s_wt[k + 3] + s_bt[k + 3]));
        } else {
            float4 v = *(const float4*)&msg[(size_t)(m0 + row) * 128 + (c4 - 32) * 4];
            o.x = to_tf32(v.x); o.y = to_tf32(v.y);
            o.z = to_tf32(v.z); o.w = to_tf32(v.w);
        }
        *(float4*)&As[row * AFULL + c4 * 4] = o;
    }
    fill_B(B0, We, 0, t);
    __syncthreads();

    float acc[2][8][4];
    #pragma unroll
    for (int mm = 0; mm < 2; mm++)
        #pragma unroll
        for (int nn = 0; nn < 8; nn++)
            #pragma unroll
            for (int r = 0; r < 4; r++) acc[mm][nn][r] = 0.0f;

    #pragma unroll
    for (int kt = 0; kt < 8; kt++) {
        float* cur = (kt & 1) ? B1 : B0;
        float* nxt = (kt & 1) ? B0 : B1;
        if (kt < 7) fill_B(nxt, We, kt + 1, t);
        gemm_compute(As, cur, acc, kt, wm, wn, g, i);
        __syncthreads();
    }

    // epilogue: store e; alpha partials in smem; finalize scale + segment max.
    const int head = wn >> 1;
    #pragma unroll
    for (int mm = 0; mm < 2; mm++) {
        int lr = wm * 32 + mm * 16 + g;
        int e0 = m0 + lr, e1 = e0 + 8;
        int s0 = s_src[lr], d0 = s_dst[lr];
        int s1 = s_src[lr + 8], d1 = s_dst[lr + 8];
        float pa = 0.0f, pb = 0.0f;
        #pragma unroll
        for (int nn = 0; nn < 8; nn++) {
            int cc = wn * 64 + nn * 8 + i * 2;
            float2 ev0; ev0.x = acc[mm][nn][0]; ev0.y = acc[mm][nn][1];
            float2 ev1; ev1.x = acc[mm][nn][2]; ev1.y = acc[mm][nn][3];
            *(float2*)&g_e[(size_t)e0 * 256 + cc] = ev0;
            *(float2*)&g_e[(size_t)e1 * 256 + cc] = ev1;
            float2 q0 = *(const float2*)&g_q[(size_t)d0 * 256 + cc];
            float2 k0 = *(const float2*)&g_k[(size_t)s0 * 256 + cc];
            float2 q1 = *(const float2*)&g_q[(size_t)d1 * 256 + cc];
            float2 k1 = *(const float2*)&g_k[(size_t)s1 * 256 + cc];
            pa += q0.x * (k0.x + ev0.x) + q0.y * (k0.y + ev0.y);
            pb += q1.x * (k1.x + ev1.x) + q1.y * (k1.y + ev1.y);
        }
        pa += __shfl_xor_sync(0xffffffffu, pa, 1);
        pa += __shfl_xor_sync(0xffffffffu, pa, 2);
        pb += __shfl_xor_sync(0xffffffffu, pb, 1);
        pb += __shfl_xor_sync(0xffffffffu, pb, 2);
        if (i == 0) {
            atomicAdd(&s_alpha[lr * 2 + head], pa);
            atomicAdd(&s_alpha[(lr + 8) * 2 + head], pb);
        }
    }
    __syncthreads();

    if (t < 256) {
        int row = t >> 1, h = t & 1;
        float a = s_alpha[t] * 0.08838834764831845f;   // 1/sqrt(128)
        g_alpha[(size_t)(m0 + row) * 2 + h] = a;
        atomicMaxFloat(&g_amax[s_dst[row] * 2 + h], a);
    }
}

// ---------------- K3: exp + segment sum ----------------
__global__ void alpha_exp_kernel(const int* __restrict__ ei) {
    int idx = blockIdx.x * blockDim.x + threadIdx.x;
    if (idx >= 2 * EE) return;
    int e = idx >> 1, h = idx & 1;
    int d = ei[EE + e];
    float w = __expf(g_alpha[idx] - g_amax[d * 2 + h]);
    g_alpha[idx] = w;
    atomicAdd(&g_asum[d * 2 + h], w);
}

// ---------------- K4: weighted aggregate (vector RED) ----------------
__global__ __launch_bounds__(256) void aggregate_kernel(
    const int* __restrict__ ei, float* __restrict__ out)
{
    int warp = (int)((blockIdx.x * (unsigned)blockDim.x + threadIdx.x) >> 5);
    int lane = threadIdx.x & 31;
    if (warp >= EE) return;
    int e = warp;
    int sidx = ei[e];
    int didx = ei[EE + e];
    int col = lane * 8;
    int h = col >> 7;
    float coef = g_alpha[(size_t)e * 2 + h] / (g_asum[didx * 2 + h] + 1e-16f);
    const float4* vp = (const float4*)&g_v[(size_t)sidx * 256 + col];
    const float4* ep = (const float4*)&g_e[(size_t)e * 256 + col];
    float* op = &out[(size_t)didx * 256 + col];
    #pragma unroll
    for (int r = 0; r < 2; r++) {
        float4 vv = vp[r];
        float4 ev = ep[r];
        float a0 = (vv.x + ev.x) * coef;
        float a1 = (vv.y + ev.y) * coef;
        float a2 = (vv.z + ev.z) * coef;
        float a3 = (vv.w + ev.w) * coef;
        asm volatile("red.global.add.v4.f32 [%0], {%1, %2, %3, %4};"
                     :: "l"(op + r * 4), "f"(a0), "f"(a1), "f"(a2), "f"(a3)
                     : "memory");
    }
}

// ---------------- launcher ----------------
extern "C" void kernel_launch(void* const* d_in, const int* in_sizes, int n_in,
                              void* d_out, int out_size) {
    const float* x           = (const float*)d_in[0];
    const float* last_update = (const float*)d_in[1];
    const float* t_arr       = (const float*)d_in[2];
    const float* msg         = (const float*)d_in[3];
    const int*   ei          = (const int*)d_in[4];
    const float* Wt          = (const float*)d_in[5];
    const float* bt          = (const float*)d_in[6];
    const float* Wq          = (const float*)d_in[7];
    const float* bq          = (const float*)d_in[8];
    const float* Wk          = (const float*)d_in[9];
    const float* bk          = (const float*)d_in[10];
    const float* Wv          = (const float*)d_in[11];
    const float* bv          = (const float*)d_in[12];
    const float* We          = (const float*)d_in[13];
    const float* Wskip       = (const float*)d_in[14];
    const float* bskip       = (const float*)d_in[15];
    float* out = (float*)d_out;

    cudaFuncSetAttribute(node_proj_kernel,
                         cudaFuncAttributeMaxDynamicSharedMemorySize, SMEM_BYTES);
    cudaFuncSetAttribute(edge_kernel,
                         cudaFuncAttributeMaxDynamicSharedMemorySize, SMEM_BYTES);

    init_kernel<<<(2 * NN + 255) / 256, 256>>>();

    dim3 g1(4, (NN + 127) / 128);
    node_proj_kernel<<<g1, 512, SMEM_BYTES>>>(x, Wq, bq, Wk, bk, Wv, bv, Wskip, bskip, out);

    edge_kernel<<<EE / 128, 512, SMEM_BYTES>>>(last_update, t_arr, msg, ei, Wt, bt, We);

    alpha_exp_kernel<<<(2 * EE + 255) / 256, 256>>>(ei);
    aggregate_kernel<<<(EE * 32 + 255) / 256, 256>>>(ei, out);
}